// round 7
// baseline (speedup 1.0000x reference)
#include <cuda_runtime.h>

#define NGR  64
#define NN   2048
#define EPG  16384          // edges per graph
#define KK   410
#define HH   3
#define CC   20
#define T    512
#define RANKC (NN - KK)     // 1638: prefix-count threshold

// ---------------- dynamic smem layout (bytes) -------------------------------
// Region A: hh1/x1 rows of 12 floats (98304 B) -> later hG rows of 64 (104960 B)
#define SZ_A     104960
#define O_CSR    SZ_A                   // int[16384]
#define O_CNT    (O_CSR + 65536)        // int[2048]
#define O_OFF    (O_CNT + 8192)         // int[2048]
#define O_CUR    (O_OFF + 8192)         // cursors (P3); enc u32[2048] (P6+)
#define O_DINV   (O_CUR + 8192)         // float[2048]
#define O_HSS    (O_DINV + 8192)        // hss (P5-6); bins (select); als+perm (P8+)
#define O_SCORE  (O_HSS + 8192)         // score (P6-P8); ald (P8+)
#define O_NEW    (O_SCORE + 8192)       // members (select); newidx (P9); finals
#define SMEM_TOTAL (O_NEW + 8192)       // 227840

// sub-offsets
#define O_ALS    O_HSS                  // float[410*3]
#define O_PERM   (O_HSS + 4920)         // int[410]
#define O_PART   O_NEW                  // float[8*60]
#define O_GSUM   (O_NEW + 1920)         // float[60]
#define O_HB     (O_NEW + 2176)         // float[30]
#define O_ZB     (O_NEW + 2304)         // float[3]

__device__ __forceinline__ float lrelu(float x) { return x > 0.f ? x : 0.2f * x; }
__device__ __forceinline__ unsigned encf(float f) {
    unsigned u = __float_as_uint(f);
    return (u & 0x80000000u) ? ~u : (u | 0x80000000u);
}

// block-wide exclusive scan of per-thread sums (all 512 threads must call)
__device__ __forceinline__ int scan_ex(int s, int t, int* wsum) {
    __syncthreads();                       // protect wsum reuse
    int lane = t & 31, wid = t >> 5;
    int x = s;
#pragma unroll
    for (int d = 1; d < 32; d <<= 1) {
        int y = __shfl_up_sync(0xFFFFFFFFu, x, d);
        if (lane >= d) x += y;
    }
    if (lane == 31) wsum[wid] = x;
    __syncthreads();
    if (t == 0) {
        int run = 0;
#pragma unroll
        for (int w = 0; w < 16; w++) { int tmp = wsum[w]; wsum[w] = run; run += tmp; }
    }
    __syncthreads();
    return wsum[wid] + x - s;
}

__global__ void __launch_bounds__(T, 1)
k_mega(const float* __restrict__ x,
       const int* __restrict__ src, const int* __restrict__ dst,
       const float* __restrict__ W1, const float* __restrict__ b1,
       const float* __restrict__ Ws, const float* __restrict__ bs,
       const float* __restrict__ Wg,
       const float* __restrict__ a_src, const float* __restrict__ a_dst,
       const float* __restrict__ bg,
       const float* __restrict__ Wf1, const float* __restrict__ bf1,
       const float* __restrict__ Wf2, const float* __restrict__ bf2,
       float* __restrict__ out)
{
    extern __shared__ char sm[];
    float*    s_hx   = (float*)(sm);                 // rows of 12
    float*    s_hG   = (float*)(sm);                 // rows of 64 (late)
    int*      s_csr  = (int*)(sm + O_CSR);
    int*      s_cnt  = (int*)(sm + O_CNT);
    int*      s_off  = (int*)(sm + O_OFF);
    int*      s_cur  = (int*)(sm + O_CUR);
    unsigned* s_enc  = (unsigned*)(sm + O_CUR);      // after P3
    float*    s_dinv = (float*)(sm + O_DINV);
    float*    s_hss  = (float*)(sm + O_HSS);
    int*      s_bins = (int*)(sm + O_HSS);           // select phase
    float*    s_als  = (float*)(sm + O_ALS);         // P8+
    int*      s_perm = (int*)(sm + O_PERM);          // P8+
    float*    s_scr  = (float*)(sm + O_SCORE);
    float*    s_ald  = (float*)(sm + O_SCORE);       // P8+
    int*      s_mem  = (int*)(sm + O_NEW);           // select members
    int*      s_new  = (int*)(sm + O_NEW);           // P9
    float*    s_part = (float*)(sm + O_PART);
    float*    s_gsum = (float*)(sm + O_GSUM);
    float*    s_hb   = (float*)(sm + O_HB);
    float*    s_zb   = (float*)(sm + O_ZB);

    __shared__ float W1s[50], Wss[10], b1s[10], Wgs[600], asr[60], ads[60];
    __shared__ int wsum[16];
    __shared__ unsigned redmn[16], redmx[16];
    __shared__ unsigned sMn, sMx;
    __shared__ int sBstar, sR, sM;
    __shared__ unsigned long long sKT;

    const int g = blockIdx.x;
    const int t = threadIdx.x;
    const int ebase = g * EPG;
    const int nbase = g * NN;
    const float bs0 = bs[0];

    // ---- P0: init + weight staging ----
    for (int i = t; i < NN; i += T) s_cnt[i] = 0;
    if (t < 50) W1s[t] = W1[t];
    if (t < 10) { Wss[t] = Ws[t]; b1s[t] = b1[t]; }
    for (int k = t; k < 600; k += T) Wgs[k] = Wg[k];
    if (t < 60) { asr[t] = a_src[t]; ads[t] = a_dst[t]; }
    if (t == 0) sM = 0;
    __syncthreads();

    // ---- P1: degree count ----
    for (int e = t; e < EPG; e += T)
        atomicAdd(&s_cnt[dst[ebase + e] & (NN - 1)], 1);

    // ---- P2: dinv + exclusive scan of cnt -> off, cur ----
    {
        __syncthreads();
        int v[4], i0 = t * 4;
#pragma unroll
        for (int q = 0; q < 4; q++) {
            v[q] = s_cnt[i0 + q];
            s_dinv[i0 + q] = rsqrtf((float)v[q] + 1.0f);
        }
        int ex = scan_ex(v[0] + v[1] + v[2] + v[3], t, wsum);
#pragma unroll
        for (int q = 0; q < 4; q++) { s_off[i0 + q] = ex; s_cur[i0 + q] = ex; ex += v[q]; }
    }
    __syncthreads();

    // ---- P3: packed CSR scatter ----
    for (int e = t; e < EPG; e += T) {
        int d = dst[ebase + e] & (NN - 1);
        int s = src[ebase + e] & (NN - 1);
        s_csr[atomicAdd(&s_cur[d], 1)] = s;
    }

    // ---- P4: hh1 = (x@W1)*dinv (12-wide rows, zero pad) ----
    __syncthreads();
    for (int i = t; i < NN; i += T) {
        float xi[5];
#pragma unroll
        for (int c = 0; c < 5; c++) xi[c] = x[(nbase + i) * 5 + c];
        float dv = s_dinv[i];
        float h[12];
#pragma unroll
        for (int k = 0; k < 10; k++) {
            float v = 0.f;
#pragma unroll
            for (int c = 0; c < 5; c++) v += xi[c] * W1s[c * 10 + k];
            h[k] = v * dv;
        }
        h[10] = 0.f; h[11] = 0.f;
        float4* o = (float4*)&s_hx[i * 12];
        o[0] = make_float4(h[0], h[1], h[2], h[3]);
        o[1] = make_float4(h[4], h[5], h[6], h[7]);
        o[2] = make_float4(h[8], h[9], h[10], h[11]);
    }
    __syncthreads();

    // ---- P5: GCN1 gather (float4) -> x1 in place + fused scorer hss ----
    {
        float4 a[4][3];
#pragma unroll
        for (int q = 0; q < 4; q++) {
            int i = t + q * T;
            const float4* me = (const float4*)&s_hx[i * 12];
            a[q][0] = me[0]; a[q][1] = me[1]; a[q][2] = me[2];
            int e0 = s_off[i], e1 = e0 + s_cnt[i];
            for (int e = e0; e < e1; e++) {
                const float4* r = (const float4*)&s_hx[s_csr[e] * 12];
                float4 r0 = r[0], r1 = r[1], r2 = r[2];
                a[q][0].x += r0.x; a[q][0].y += r0.y; a[q][0].z += r0.z; a[q][0].w += r0.w;
                a[q][1].x += r1.x; a[q][1].y += r1.y; a[q][1].z += r1.z; a[q][1].w += r1.w;
                a[q][2].x += r2.x; a[q][2].y += r2.y;
            }
        }
        __syncthreads();
#pragma unroll
        for (int q = 0; q < 4; q++) {
            int i = t + q * T;
            float dv = s_dinv[i];
            float v[10] = {a[q][0].x, a[q][0].y, a[q][0].z, a[q][0].w,
                           a[q][1].x, a[q][1].y, a[q][1].z, a[q][1].w,
                           a[q][2].x, a[q][2].y};
            float hs = 0.f;
#pragma unroll
            for (int k = 0; k < 10; k++) {
                v[k] = v[k] * dv + b1s[k];
                hs += v[k] * Wss[k];
            }
            float4* o = (float4*)&s_hx[i * 12];
            o[0] = make_float4(v[0], v[1], v[2], v[3]);
            o[1] = make_float4(v[4], v[5], v[6], v[7]);
            o[2] = make_float4(v[8], v[9], 0.f, 0.f);
            s_hss[i] = hs * dv;
        }
    }
    __syncthreads();

    // ---- P6: scorer gather -> score + enc ----
    for (int i = t; i < NN; i += T) {
        float sc = s_hss[i];
        int e0 = s_off[i], e1 = e0 + s_cnt[i];
        for (int e = e0; e < e1; e++) sc += s_hss[s_csr[e]];
        sc = sc * s_dinv[i] + bs0;
        s_scr[i] = sc;
        s_enc[i] = encf(sc);
    }
    __syncthreads();

    // ---- P7: top-K selection via histogram (hss region now free -> bins) ----
    {
        // min/max reduce of enc
        unsigned mn = 0xFFFFFFFFu, mx = 0u;
        int i0 = t * 4;
#pragma unroll
        for (int q = 0; q < 4; q++) {
            unsigned e = s_enc[i0 + q];
            mn = min(mn, e); mx = max(mx, e);
        }
#pragma unroll
        for (int d = 16; d; d >>= 1) {
            mn = min(mn, __shfl_down_sync(0xFFFFFFFFu, mn, d));
            mx = max(mx, __shfl_down_sync(0xFFFFFFFFu, mx, d));
        }
        if ((t & 31) == 0) { redmn[t >> 5] = mn; redmx[t >> 5] = mx; }
        // zero bins
#pragma unroll
        for (int q = 0; q < 4; q++) s_bins[i0 + q] = 0;
        __syncthreads();
        if (t == 0) {
            unsigned m0 = 0xFFFFFFFFu, m1 = 0u;
#pragma unroll
            for (int w = 0; w < 16; w++) { m0 = min(m0, redmn[w]); m1 = max(m1, redmx[w]); }
            sMn = m0; sMx = m1;
        }
        __syncthreads();
        unsigned bmn = sMn;
        float scale = (sMx > bmn) ? 2047.0f / (float)(sMx - bmn) : 0.0f;
        // histogram
#pragma unroll
        for (int q = 0; q < 4; q++) {
            int b = (int)((float)(s_enc[i0 + q] - bmn) * scale);
            b = b > 2047 ? 2047 : b;
            atomicAdd(&s_bins[b], 1);
        }
        __syncthreads();
        // prefix scan of bins; find threshold bin crossing RANKC
        int v[4];
#pragma unroll
        for (int q = 0; q < 4; q++) v[q] = s_bins[i0 + q];
        int run = scan_ex(v[0] + v[1] + v[2] + v[3], t, wsum);
#pragma unroll
        for (int q = 0; q < 4; q++) {
            int incl = run + v[q];
            if (run <= RANKC && incl > RANKC) {
                sBstar = i0 + q;
                sR = 410 - (NN - incl);     // rank needed inside threshold bin
            }
            run = incl;
        }
        __syncthreads();
        // collect members of threshold bin
        int bstar = sBstar;
#pragma unroll
        for (int q = 0; q < 4; q++) {
            int i = i0 + q;
            int b = (int)((float)(s_enc[i] - bmn) * scale);
            b = b > 2047 ? 2047 : b;
            if (b == bstar) s_mem[atomicAdd(&sM, 1)] = i;
        }
        __syncthreads();
        // warp 0: extract the sR-th largest (enc, 2047-idx) key among members
        if (t < 32) {
            int m = sM, r = sR;
            for (int it = 0; it < r; it++) {
                unsigned long long best = 0ull; int bpos = -1;
                for (int k = t; k < m; k += 32) {
                    int idx = s_mem[k];
                    if (idx < 0) continue;
                    unsigned long long key =
                        ((unsigned long long)s_enc[idx] << 11) | (unsigned)(2047 - idx);
                    if (key > best) { best = key; bpos = k; }
                }
#pragma unroll
                for (int d = 16; d; d >>= 1) {
                    unsigned long long ob = __shfl_down_sync(0xFFFFFFFFu, best, d);
                    int op = __shfl_down_sync(0xFFFFFFFFu, bpos, d);
                    if (ob > best) { best = ob; bpos = op; }
                }
                best = __shfl_sync(0xFFFFFFFFu, best, 0);
                bpos = __shfl_sync(0xFFFFFFFFu, bpos, 0);
                if (t == 0) {
                    s_mem[bpos] = -1;
                    if (it == r - 1) sKT = best;
                }
                __syncwarp();
            }
        }
        __syncthreads();
        // deterministic compaction: keep iff key >= KT (exactly 410, jax tie order)
        unsigned long long KT = sKT;
        int p[4];
#pragma unroll
        for (int q = 0; q < 4; q++) {
            int i = i0 + q;
            unsigned long long key =
                ((unsigned long long)s_enc[i] << 11) | (unsigned)(2047 - i);
            p[q] = (key >= KT) ? 1 : 0;
        }
        int slot = scan_ex(p[0] + p[1] + p[2] + p[3], t, wsum);
#pragma unroll
        for (int q = 0; q < 4; q++) {
            int i = i0 + q;
            if (p[q]) { s_perm[slot] = i; s_new[i] = slot; }
            else      { s_new[i] = -1; }
            slot += p[q];
        }
    }
    __syncthreads();

    // ---- P8: pooled precompute: hG = (x1*tanh(score)) @ Wg ; als/ald ----
    float hg[60], als3[3], ald3[3];
    int node = -1;
    if (t < KK) {
        node = s_perm[t];
        float gate = tanhf(s_scr[node]);
        float xp[10];
#pragma unroll
        for (int c = 0; c < 10; c++) xp[c] = s_hx[node * 12 + c] * gate;
#pragma unroll
        for (int h = 0; h < HH; h++) { als3[h] = 0.f; ald3[h] = 0.f; }
#pragma unroll
        for (int h = 0; h < HH; h++) {
#pragma unroll
            for (int c = 0; c < CC; c++) {
                int k = h * CC + c;
                float v = 0.f;
#pragma unroll
                for (int q = 0; q < 10; q++) v += xp[q] * Wgs[q * 60 + k];
                hg[k] = v;
                als3[h] += v * asr[k];
                ald3[h] += v * ads[k];
            }
        }
    }
    __syncthreads();   // all reads of s_hx/s_scr done
    if (t < KK) {
#pragma unroll
        for (int k = 0; k < 60; k++) s_hG[t * 64 + k] = hg[k];
#pragma unroll
        for (int h = 0; h < HH; h++) {
            s_als[t * 3 + h] = als3[h];
            s_ald[t * 3 + h] = ald3[h];
        }
    }
    __syncthreads();

    // ---- P9: GAT softmax-aggregate (logits ~1e-2: exp w/o max-sub exact) ----
    float4 oa[15];
    if (t < KK) {
        float den[3];
#pragma unroll
        for (int h = 0; h < HH; h++)
            den[h] = __expf(lrelu(s_als[t * 3 + h] + s_ald[t * 3 + h]));
        const float4* self = (const float4*)&s_hG[t * 64];
#pragma unroll
        for (int k = 0; k < 15; k++) {
            float w = den[k / 5];
            float4 v = self[k];
            oa[k] = make_float4(v.x * w, v.y * w, v.z * w, v.w * w);
        }
        float aldj0 = s_ald[t * 3 + 0], aldj1 = s_ald[t * 3 + 1], aldj2 = s_ald[t * 3 + 2];
        int e0 = s_off[node], e1 = e0 + s_cnt[node];
        for (int e = e0; e < e1; e++) {
            int sj = s_new[s_csr[e]];
            if (sj < 0) continue;
            float w0 = __expf(lrelu(s_als[sj * 3 + 0] + aldj0));
            float w1 = __expf(lrelu(s_als[sj * 3 + 1] + aldj1));
            float w2 = __expf(lrelu(s_als[sj * 3 + 2] + aldj2));
            den[0] += w0; den[1] += w1; den[2] += w2;
            const float4* row = (const float4*)&s_hG[sj * 64];
#pragma unroll
            for (int k = 0; k < 15; k++) {
                float w = (k < 5) ? w0 : (k < 10 ? w1 : w2);
                float4 v = row[k];
                oa[k].x += v.x * w; oa[k].y += v.y * w;
                oa[k].z += v.z * w; oa[k].w += v.w * w;
            }
        }
        float iv[3] = {1.f / den[0], 1.f / den[1], 1.f / den[2]};
#pragma unroll
        for (int k = 0; k < 15; k++) {
            float w = iv[k / 5];
            oa[k].x *= w; oa[k].y *= w; oa[k].z *= w; oa[k].w *= w;
        }
    }
    __syncthreads();   // all reads of s_hG done
    if (t < KK) {
        float4* o = (float4*)&s_hG[t * 64];
#pragma unroll
        for (int k = 0; k < 15; k++) o[k] = oa[k];
    }
    __syncthreads();

    // ---- readout reduction over 410 rows ----
    {
        int col = t & 63, grp = t >> 6;
        if (col < 60) {
            float a = 0.f;
            for (int r = grp; r < KK; r += 8) a += s_hG[r * 64 + col];
            s_part[grp * 60 + col] = a;
        }
    }
    __syncthreads();
    if (t < 60) {
        float a = 0.f;
#pragma unroll
        for (int q = 0; q < 8; q++) a += s_part[q * 60 + t];
        s_gsum[t] = a + (float)KK * bg[t];
    }
    __syncthreads();

    // ---- MLP + log_softmax ----
    if (t < 30) {
        float v = bf1[t];
#pragma unroll
        for (int c = 0; c < 60; c++) v += s_gsum[c] * Wf1[c * 30 + t];
        s_hb[t] = v > 0.f ? v : 0.f;
    }
    __syncthreads();
    if (t < 3) {
        float v = bf2[t];
#pragma unroll
        for (int c = 0; c < 30; c++) v += s_hb[c] * Wf2[c * 3 + t];
        s_zb[t] = v;
    }
    __syncthreads();
    if (t == 0) {
        float m = fmaxf(s_zb[0], fmaxf(s_zb[1], s_zb[2]));
        float lse = logf(expf(s_zb[0] - m) + expf(s_zb[1] - m) + expf(s_zb[2] - m)) + m;
        out[g * 3 + 0] = s_zb[0] - lse;
        out[g * 3 + 1] = s_zb[1] - lse;
        out[g * 3 + 2] = s_zb[2] - lse;
    }
}

// ---------------- launch -----------------------------------------------------
extern "C" void kernel_launch(void* const* d_in, const int* in_sizes, int n_in,
                              void* d_out, int out_size) {
    const float* x     = (const float*)d_in[0];
    const int*   src   = (const int*)d_in[1];
    const int*   dst   = (const int*)d_in[2];
    const float* W1    = (const float*)d_in[4];
    const float* b1    = (const float*)d_in[5];
    const float* Ws    = (const float*)d_in[6];
    const float* bs    = (const float*)d_in[7];
    const float* Wg    = (const float*)d_in[8];
    const float* a_src = (const float*)d_in[9];
    const float* a_dst = (const float*)d_in[10];
    const float* bg    = (const float*)d_in[11];
    const float* Wf1   = (const float*)d_in[12];
    const float* bf1   = (const float*)d_in[13];
    const float* Wf2   = (const float*)d_in[14];
    const float* bf2   = (const float*)d_in[15];
    float* out = (float*)d_out;

    static int attr_set = 0;
    if (!attr_set) {
        cudaFuncSetAttribute(k_mega, cudaFuncAttributeMaxDynamicSharedMemorySize,
                             SMEM_TOTAL);
        attr_set = 1;
    }
    k_mega<<<NGR, T, SMEM_TOTAL>>>(x, src, dst, W1, b1, Ws, bs, Wg, a_src, a_dst,
                                   bg, Wf1, bf1, Wf2, bf2, out);
}

// round 8
// speedup vs baseline: 1.6398x; 1.6398x over previous
#include <cuda_runtime.h>

#define NGR  64
#define NN   2048
#define EPG  16384          // edges per graph
#define KK   410
#define HH   3
#define CC   20
#define T    512

// ---------------- dynamic smem layout (bytes) -------------------------------
// Region A: hh1/x1 rows of 12 floats (98304 B) -> later hG rows of 64 (104960 B)
#define SZ_A     104960
#define O_CSR    SZ_A                   // int[16384]
#define O_CNT    (O_CSR + 65536)        // int[2048]
#define O_OFF    (O_CNT + 8192)         // int[2048]
#define O_CUR    (O_OFF + 8192)         // cursors (P3); enc u32[2048] (P6+)
#define O_DINV   (O_CUR + 8192)         // float[2048]
#define O_HSS    (O_DINV + 8192)        // hss (P5-6); radix bins; als+perm (P8+)
#define O_SCORE  (O_HSS + 8192)         // score (P6-P8); ald (P8+)
#define O_NEW    (O_SCORE + 8192)       // newidx; readout temps at end
#define SMEM_TOTAL (O_NEW + 8192)       // 227840

// sub-offsets
#define O_ALS    O_HSS                  // float[410*3]
#define O_PERM   (O_HSS + 4920)         // int[410]
#define O_PART   O_NEW                  // float[8*60]  (after s_new is dead)
#define O_GSUM   (O_NEW + 1920)         // float[60]
#define O_HB     (O_NEW + 2176)         // float[30]
#define O_ZB     (O_NEW + 2304)         // float[3]

__device__ __forceinline__ float lrelu(float x) { return x > 0.f ? x : 0.2f * x; }
__device__ __forceinline__ unsigned encf(float f) {
    unsigned u = __float_as_uint(f);
    return (u & 0x80000000u) ? ~u : (u | 0x80000000u);
}

// block-wide exclusive scan of per-thread sums (all 512 threads must call)
__device__ __forceinline__ int scan_ex(int s, int t, int* wsum) {
    __syncthreads();                       // protect wsum reuse
    int lane = t & 31, wid = t >> 5;
    int x = s;
#pragma unroll
    for (int d = 1; d < 32; d <<= 1) {
        int y = __shfl_up_sync(0xFFFFFFFFu, x, d);
        if (lane >= d) x += y;
    }
    if (lane == 31) wsum[wid] = x;
    __syncthreads();
    if (t == 0) {
        int run = 0;
#pragma unroll
        for (int w = 0; w < 16; w++) { int tmp = wsum[w]; wsum[w] = run; run += tmp; }
    }
    __syncthreads();
    return wsum[wid] + x - s;
}

__global__ void __launch_bounds__(T, 1)
k_mega(const float* __restrict__ x,
       const int* __restrict__ src, const int* __restrict__ dst,
       const float* __restrict__ W1, const float* __restrict__ b1,
       const float* __restrict__ Ws, const float* __restrict__ bs,
       const float* __restrict__ Wg,
       const float* __restrict__ a_src, const float* __restrict__ a_dst,
       const float* __restrict__ bg,
       const float* __restrict__ Wf1, const float* __restrict__ bf1,
       const float* __restrict__ Wf2, const float* __restrict__ bf2,
       float* __restrict__ out)
{
    extern __shared__ char sm[];
    float*    s_hx   = (float*)(sm);                 // rows of 12
    float*    s_hG   = (float*)(sm);                 // rows of 64 (late)
    int*      s_csr  = (int*)(sm + O_CSR);
    int*      s_cnt  = (int*)(sm + O_CNT);
    int*      s_off  = (int*)(sm + O_OFF);
    int*      s_cur  = (int*)(sm + O_CUR);
    unsigned* s_enc  = (unsigned*)(sm + O_CUR);      // after P3
    float*    s_dinv = (float*)(sm + O_DINV);
    float*    s_hss  = (float*)(sm + O_HSS);
    int*      s_bins = (int*)(sm + O_HSS);           // radix bins (256)
    float*    s_als  = (float*)(sm + O_ALS);         // P8+
    int*      s_perm = (int*)(sm + O_PERM);          // P8+
    float*    s_scr  = (float*)(sm + O_SCORE);
    float*    s_ald  = (float*)(sm + O_SCORE);       // P8+
    int*      s_new  = (int*)(sm + O_NEW);
    float*    s_part = (float*)(sm + O_PART);
    float*    s_gsum = (float*)(sm + O_GSUM);
    float*    s_hb   = (float*)(sm + O_HB);
    float*    s_zb   = (float*)(sm + O_ZB);

    __shared__ float W1s[50], Wss[10], b1s[10], Wgs[600], asr[60], ads[60];
    __shared__ int wsum[16];
    __shared__ unsigned sPrefix;
    __shared__ int sNeed, sDig, sRem;

    const int g = blockIdx.x;
    const int t = threadIdx.x;
    const int ebase = g * EPG;
    const int nbase = g * NN;
    const float bs0 = bs[0];

    // ---- P0: init + weight staging ----
    for (int i = t; i < NN; i += T) s_cnt[i] = 0;
    if (t < 50) W1s[t] = W1[t];
    if (t < 10) { Wss[t] = Ws[t]; b1s[t] = b1[t]; }
    for (int k = t; k < 600; k += T) Wgs[k] = Wg[k];
    if (t < 60) { asr[t] = a_src[t]; ads[t] = a_dst[t]; }
    __syncthreads();

    // ---- P1: degree count ----
    for (int e = t; e < EPG; e += T)
        atomicAdd(&s_cnt[dst[ebase + e] & (NN - 1)], 1);

    // ---- P2: dinv + exclusive scan of cnt -> off, cur ----
    {
        __syncthreads();
        int v[4], i0 = t * 4;
#pragma unroll
        for (int q = 0; q < 4; q++) {
            v[q] = s_cnt[i0 + q];
            s_dinv[i0 + q] = rsqrtf((float)v[q] + 1.0f);
        }
        int ex = scan_ex(v[0] + v[1] + v[2] + v[3], t, wsum);
#pragma unroll
        for (int q = 0; q < 4; q++) { s_off[i0 + q] = ex; s_cur[i0 + q] = ex; ex += v[q]; }
    }
    __syncthreads();

    // ---- P3: packed CSR scatter ----
    for (int e = t; e < EPG; e += T) {
        int d = dst[ebase + e] & (NN - 1);
        int s = src[ebase + e] & (NN - 1);
        s_csr[atomicAdd(&s_cur[d], 1)] = s;
    }

    // ---- P4: hh1 = (x@W1)*dinv (12-wide rows, zero pad) ----
    __syncthreads();
    for (int i = t; i < NN; i += T) {
        float xi[5];
#pragma unroll
        for (int c = 0; c < 5; c++) xi[c] = x[(nbase + i) * 5 + c];
        float dv = s_dinv[i];
        float h[12];
#pragma unroll
        for (int k = 0; k < 10; k++) {
            float v = 0.f;
#pragma unroll
            for (int c = 0; c < 5; c++) v += xi[c] * W1s[c * 10 + k];
            h[k] = v * dv;
        }
        h[10] = 0.f; h[11] = 0.f;
        float4* o = (float4*)&s_hx[i * 12];
        o[0] = make_float4(h[0], h[1], h[2], h[3]);
        o[1] = make_float4(h[4], h[5], h[6], h[7]);
        o[2] = make_float4(h[8], h[9], h[10], h[11]);
    }
    __syncthreads();

    // ---- P5: GCN1 gather (float4) -> x1 in place + fused scorer hss ----
    {
        float4 a[4][3];
#pragma unroll
        for (int q = 0; q < 4; q++) {
            int i = t + q * T;
            const float4* me = (const float4*)&s_hx[i * 12];
            a[q][0] = me[0]; a[q][1] = me[1]; a[q][2] = me[2];
            int e0 = s_off[i], e1 = e0 + s_cnt[i];
            for (int e = e0; e < e1; e++) {
                const float4* r = (const float4*)&s_hx[s_csr[e] * 12];
                float4 r0 = r[0], r1 = r[1], r2 = r[2];
                a[q][0].x += r0.x; a[q][0].y += r0.y; a[q][0].z += r0.z; a[q][0].w += r0.w;
                a[q][1].x += r1.x; a[q][1].y += r1.y; a[q][1].z += r1.z; a[q][1].w += r1.w;
                a[q][2].x += r2.x; a[q][2].y += r2.y;
            }
        }
        __syncthreads();
#pragma unroll
        for (int q = 0; q < 4; q++) {
            int i = t + q * T;
            float dv = s_dinv[i];
            float v[10] = {a[q][0].x, a[q][0].y, a[q][0].z, a[q][0].w,
                           a[q][1].x, a[q][1].y, a[q][1].z, a[q][1].w,
                           a[q][2].x, a[q][2].y};
            float hs = 0.f;
#pragma unroll
            for (int k = 0; k < 10; k++) {
                v[k] = v[k] * dv + b1s[k];
                hs += v[k] * Wss[k];
            }
            float4* o = (float4*)&s_hx[i * 12];
            o[0] = make_float4(v[0], v[1], v[2], v[3]);
            o[1] = make_float4(v[4], v[5], v[6], v[7]);
            o[2] = make_float4(v[8], v[9], 0.f, 0.f);
            s_hss[i] = hs * dv;
        }
    }
    __syncthreads();

    // ---- P6: scorer gather -> score + enc ----
    for (int i = t; i < NN; i += T) {
        float sc = s_hss[i];
        int e0 = s_off[i], e1 = e0 + s_cnt[i];
        for (int e = e0; e < e1; e++) sc += s_hss[s_csr[e]];
        sc = sc * s_dinv[i] + bs0;
        s_scr[i] = sc;
        s_enc[i] = encf(sc);
    }
    __syncthreads();

    // ---- P7: top-K via 8-bit radix select on enc (descending), then compact --
    {
        if (t == 0) { sPrefix = 0u; sNeed = KK; }
        __syncthreads();
        int i0 = t * 4;
#pragma unroll
        for (int shift = 24; shift >= 0; shift -= 8) {
            if (t < 256) s_bins[t] = 0;
            __syncthreads();
            unsigned pfx = sPrefix;
#pragma unroll
            for (int q = 0; q < 4; q++) {
                unsigned e = s_enc[i0 + q];
                bool match = (shift == 24) || ((e >> (shift + 8)) == pfx);
                if (match) atomicAdd(&s_bins[(e >> shift) & 255], 1);
            }
            __syncthreads();
            // descending cumulative: thread t<256 owns digit 255-t
            int mycount = (t < 256) ? s_bins[255 - t] : 0;
            int ex = scan_ex(mycount, t, wsum);
            if (t < 256) {
                int need = sNeed;
                if (ex < need && need <= ex + mycount) {
                    sDig = 255 - t;          // threshold digit this level
                    sRem = need - ex;        // still needed within it
                }
            }
            __syncthreads();
            if (t == 0) { sPrefix = (sPrefix << 8) | (unsigned)sDig; sNeed = sRem; }
            __syncthreads();
        }
        unsigned KT = sPrefix;   // KK-th largest enc (tie value)
        int tneed = sNeed;       // ties to accept (smallest index first)
        int ng = KK - tneed;     // count of strictly-greater values
        int pg[4], pt[4];
#pragma unroll
        for (int q = 0; q < 4; q++) {
            unsigned e = s_enc[i0 + q];
            pg[q] = (e > KT) ? 1 : 0;
            pt[q] = (e == KT) ? 1 : 0;
        }
        int exg = scan_ex(pg[0] + pg[1] + pg[2] + pg[3], t, wsum);
        int ext = scan_ex(pt[0] + pt[1] + pt[2] + pt[3], t, wsum);
#pragma unroll
        for (int q = 0; q < 4; q++) {
            int i = i0 + q;
            int slot = -1;
            if (pg[q]) slot = exg;
            else if (pt[q] && ext < tneed) slot = ng + ext;
            if (slot >= 0) { s_perm[slot] = i; s_new[i] = slot; }
            else s_new[i] = -1;
            exg += pg[q];
            ext += pt[q];
        }
    }
    __syncthreads();

    // ---- P8: pooled precompute: hG = (x1*tanh(score)) @ Wg ; als/ald ----
    float hg[60], als3[3], ald3[3];
    int node = -1;
    if (t < KK) {
        node = s_perm[t];
        float gate = tanhf(s_scr[node]);
        float xp[10];
#pragma unroll
        for (int c = 0; c < 10; c++) xp[c] = s_hx[node * 12 + c] * gate;
#pragma unroll
        for (int h = 0; h < HH; h++) { als3[h] = 0.f; ald3[h] = 0.f; }
#pragma unroll
        for (int h = 0; h < HH; h++) {
#pragma unroll
            for (int c = 0; c < CC; c++) {
                int k = h * CC + c;
                float v = 0.f;
#pragma unroll
                for (int q = 0; q < 10; q++) v += xp[q] * Wgs[q * 60 + k];
                hg[k] = v;
                als3[h] += v * asr[k];
                ald3[h] += v * ads[k];
            }
        }
    }
    __syncthreads();   // all reads of s_hx/s_scr done
    if (t < KK) {
#pragma unroll
        for (int k = 0; k < 60; k++) s_hG[t * 64 + k] = hg[k];
#pragma unroll
        for (int h = 0; h < HH; h++) {
            s_als[t * 3 + h] = als3[h];
            s_ald[t * 3 + h] = ald3[h];
        }
    }
    __syncthreads();

    // ---- P9: GAT softmax-aggregate (logits ~1e-2: exp w/o max-sub exact) ----
    float4 oa[15];
    if (t < KK) {
        float den[3];
#pragma unroll
        for (int h = 0; h < HH; h++)
            den[h] = __expf(lrelu(s_als[t * 3 + h] + s_ald[t * 3 + h]));
        const float4* self = (const float4*)&s_hG[t * 64];
#pragma unroll
        for (int k = 0; k < 15; k++) {
            float w = den[k / 5];
            float4 v = self[k];
            oa[k] = make_float4(v.x * w, v.y * w, v.z * w, v.w * w);
        }
        float aldj0 = s_ald[t * 3 + 0], aldj1 = s_ald[t * 3 + 1], aldj2 = s_ald[t * 3 + 2];
        int e0 = s_off[node], e1 = e0 + s_cnt[node];
        for (int e = e0; e < e1; e++) {
            int sj = s_new[s_csr[e]];
            if (sj < 0) continue;
            float w0 = __expf(lrelu(s_als[sj * 3 + 0] + aldj0));
            float w1 = __expf(lrelu(s_als[sj * 3 + 1] + aldj1));
            float w2 = __expf(lrelu(s_als[sj * 3 + 2] + aldj2));
            den[0] += w0; den[1] += w1; den[2] += w2;
            const float4* row = (const float4*)&s_hG[sj * 64];
#pragma unroll
            for (int k = 0; k < 15; k++) {
                float w = (k < 5) ? w0 : (k < 10 ? w1 : w2);
                float4 v = row[k];
                oa[k].x += v.x * w; oa[k].y += v.y * w;
                oa[k].z += v.z * w; oa[k].w += v.w * w;
            }
        }
        float iv[3] = {1.f / den[0], 1.f / den[1], 1.f / den[2]};
#pragma unroll
        for (int k = 0; k < 15; k++) {
            float w = iv[k / 5];
            oa[k].x *= w; oa[k].y *= w; oa[k].z *= w; oa[k].w *= w;
        }
    }
    __syncthreads();   // all reads of s_hG done
    if (t < KK) {
        float4* o = (float4*)&s_hG[t * 64];
#pragma unroll
        for (int k = 0; k < 15; k++) o[k] = oa[k];
    }
    __syncthreads();

    // ---- readout reduction over 410 rows ----
    {
        int col = t & 63, grp = t >> 6;
        if (col < 60) {
            float a = 0.f;
            for (int r = grp; r < KK; r += 8) a += s_hG[r * 64 + col];
            s_part[grp * 60 + col] = a;
        }
    }
    __syncthreads();
    if (t < 60) {
        float a = 0.f;
#pragma unroll
        for (int q = 0; q < 8; q++) a += s_part[q * 60 + t];
        s_gsum[t] = a + (float)KK * bg[t];
    }
    __syncthreads();

    // ---- MLP + log_softmax ----
    if (t < 30) {
        float v = bf1[t];
#pragma unroll
        for (int c = 0; c < 60; c++) v += s_gsum[c] * Wf1[c * 30 + t];
        s_hb[t] = v > 0.f ? v : 0.f;
    }
    __syncthreads();
    if (t < 3) {
        float v = bf2[t];
#pragma unroll
        for (int c = 0; c < 30; c++) v += s_hb[c] * Wf2[c * 3 + t];
        s_zb[t] = v;
    }
    __syncthreads();
    if (t == 0) {
        float m = fmaxf(s_zb[0], fmaxf(s_zb[1], s_zb[2]));
        float lse = logf(expf(s_zb[0] - m) + expf(s_zb[1] - m) + expf(s_zb[2] - m)) + m;
        out[g * 3 + 0] = s_zb[0] - lse;
        out[g * 3 + 1] = s_zb[1] - lse;
        out[g * 3 + 2] = s_zb[2] - lse;
    }
}

// ---------------- launch -----------------------------------------------------
extern "C" void kernel_launch(void* const* d_in, const int* in_sizes, int n_in,
                              void* d_out, int out_size) {
    const float* x     = (const float*)d_in[0];
    const int*   src   = (const int*)d_in[1];
    const int*   dst   = (const int*)d_in[2];
    const float* W1    = (const float*)d_in[4];
    const float* b1    = (const float*)d_in[5];
    const float* Ws    = (const float*)d_in[6];
    const float* bs    = (const float*)d_in[7];
    const float* Wg    = (const float*)d_in[8];
    const float* a_src = (const float*)d_in[9];
    const float* a_dst = (const float*)d_in[10];
    const float* bg    = (const float*)d_in[11];
    const float* Wf1   = (const float*)d_in[12];
    const float* bf1   = (const float*)d_in[13];
    const float* Wf2   = (const float*)d_in[14];
    const float* bf2   = (const float*)d_in[15];
    float* out = (float*)d_out;

    static int attr_set = 0;
    if (!attr_set) {
        cudaFuncSetAttribute(k_mega, cudaFuncAttributeMaxDynamicSharedMemorySize,
                             SMEM_TOTAL);
        attr_set = 1;
    }
    k_mega<<<NGR, T, SMEM_TOTAL>>>(x, src, dst, W1, b1, Ws, bs, Wg, a_src, a_dst,
                                   bg, Wf1, bf1, Wf2, bf2, out);
}